// round 10
// baseline (speedup 1.0000x reference)
#include <cuda_runtime.h>
#include <math.h>

#define BATCH   16
#define HEADS   32
#define HDIM    128
#define NBLK    1024
#define BLKSZ   16
#define MAXB    128
#define HIDDEN  (HEADS * HDIM)      // 4096
#define S_MAX   (MAXB * BLKSZ)      // 2048
#define CHUNK   128
#define NCHUNK  (S_MAX / CHUNK)     // 16
#define EPS     1e-6f
#define NEG_BIG (-1e30f)
#define QK_SCALE 0.08838834764831845f   // 1/sqrt(128)

// Scratch (no allocations allowed in kernel_launch)
__device__ float g_pm[BATCH * HEADS * NCHUNK];              // per-chunk running max
__device__ float g_pl[BATCH * HEADS * NCHUNK];              // per-chunk sum(exp)
__device__ float g_pacc[BATCH * HEADS * NCHUNK * HDIM];     // per-chunk unnormalized acc

// ---------------------------------------------------------------------------
// Kernel 1: fused RMSNorm + flash-decoding partial attention (one 128-pos chunk)
// Grid: (NCHUNK, HEADS, BATCH), 256 threads = 8 warps.
// ---------------------------------------------------------------------------
__global__ __launch_bounds__(256) void attn_kernel(const float* __restrict__ hidden,
                                                   const float* __restrict__ w,
                                                   const float* __restrict__ kc,
                                                   const float* __restrict__ vc,
                                                   const int*   __restrict__ bt,
                                                   const int*   __restrict__ ctx_lens) {
    int chunk = blockIdx.x, h = blockIdx.y, b = blockIdx.z;
    int ctx = ctx_lens[b];
    int s0 = chunk * CHUNK;
    if (s0 >= ctx) return;                      // uniform across CTA: safe early exit
    int s_end = min(s0 + CHUNK, ctx);

    int warp = threadIdx.x >> 5;
    int lane = threadIdx.x & 31;

    // ---- fused RMSNorm: sum of squares over hidden[b, :] (L2-resident) ----
    __shared__ float red[8];
    {
        const float4* xr = reinterpret_cast<const float4*>(hidden + (size_t)b * HIDDEN);
        float4 v0 = xr[threadIdx.x];
        float4 v1 = xr[threadIdx.x + 256];
        float4 v2 = xr[threadIdx.x + 512];
        float4 v3 = xr[threadIdx.x + 768];
        float ss = v0.x*v0.x + v0.y*v0.y + v0.z*v0.z + v0.w*v0.w
                 + v1.x*v1.x + v1.y*v1.y + v1.z*v1.z + v1.w*v1.w
                 + v2.x*v2.x + v2.y*v2.y + v2.z*v2.z + v2.w*v2.w
                 + v3.x*v3.x + v3.y*v3.y + v3.z*v3.z + v3.w*v3.w;
        #pragma unroll
        for (int o = 16; o; o >>= 1) ss += __shfl_xor_sync(0xffffffffu, ss, o);
        if (lane == 0) red[warp] = ss;
    }
    __syncthreads();
    float tot = red[0] + red[1] + red[2] + red[3] + red[4] + red[5] + red[6] + red[7];
    float inv = rsqrtf(tot * (1.0f / HIDDEN) + EPS) * QK_SCALE;

    // lane-private q fragment (4 contiguous floats), norm + weight folded in
    float4 q4;
    {
        size_t qo = (size_t)b * HIDDEN + h * HDIM + lane * 4;
        float4 hx = *reinterpret_cast<const float4*>(hidden + qo);
        float4 wx = *reinterpret_cast<const float4*>(w + h * HDIM + lane * 4);
        q4 = make_float4(hx.x * inv * wx.x, hx.y * inv * wx.y,
                         hx.z * inv * wx.z, hx.w * inv * wx.w);
    }

    const int* btb = bt + b * MAXB;

    float  m = NEG_BIG, l = 0.f;
    float4 acc = make_float4(0.f, 0.f, 0.f, 0.f);

    int s = s0 + warp;
    // ---- x2 unrolled mainloop: 4 outstanding 512B streaming loads per warp ----
    for (; s + 8 < s_end; s += 16) {
        int s1 = s + 8;
        int blk0 = __ldg(btb + (s  >> 4));
        int blk1 = __ldg(btb + (s1 >> 4));
        size_t base0 = ((size_t)(blk0 * BLKSZ + (s  & 15)) * HEADS + h) * HDIM + lane * 4;
        size_t base1 = ((size_t)(blk1 * BLKSZ + (s1 & 15)) * HEADS + h) * HDIM + lane * 4;
        float4 k0 = __ldcs(reinterpret_cast<const float4*>(kc + base0));
        float4 v0 = __ldcs(reinterpret_cast<const float4*>(vc + base0));
        float4 k1 = __ldcs(reinterpret_cast<const float4*>(kc + base1));
        float4 v1 = __ldcs(reinterpret_cast<const float4*>(vc + base1));

        float d0 = k0.x*q4.x + k0.y*q4.y + k0.z*q4.z + k0.w*q4.w;
        float d1 = k1.x*q4.x + k1.y*q4.y + k1.z*q4.z + k1.w*q4.w;
        #pragma unroll
        for (int o = 16; o; o >>= 1) {          // interleaved butterflies
            d0 += __shfl_xor_sync(0xffffffffu, d0, o);
            d1 += __shfl_xor_sync(0xffffffffu, d1, o);
        }

        float m_new = fmaxf(m, fmaxf(d0, d1));
        float r  = __expf(m  - m_new);          // underflows to 0 on first iter
        float p0 = __expf(d0 - m_new);
        float p1 = __expf(d1 - m_new);
        acc.x = acc.x * r + p0 * v0.x + p1 * v1.x;
        acc.y = acc.y * r + p0 * v0.y + p1 * v1.y;
        acc.z = acc.z * r + p0 * v0.z + p1 * v1.z;
        acc.w = acc.w * r + p0 * v0.w + p1 * v1.w;
        l = l * r + p0 + p1;
        m = m_new;
    }
    // tail (at most one position per warp)
    if (s < s_end) {
        int blk = __ldg(btb + (s >> 4));
        size_t base = ((size_t)(blk * BLKSZ + (s & 15)) * HEADS + h) * HDIM + lane * 4;
        float4 k4 = __ldcs(reinterpret_cast<const float4*>(kc + base));
        float4 v4 = __ldcs(reinterpret_cast<const float4*>(vc + base));
        float dot = k4.x*q4.x + k4.y*q4.y + k4.z*q4.z + k4.w*q4.w;
        #pragma unroll
        for (int o = 16; o; o >>= 1) dot += __shfl_xor_sync(0xffffffffu, dot, o);
        float m_new = fmaxf(m, dot);
        float r = __expf(m - m_new);
        float p = __expf(dot - m_new);
        acc.x = acc.x * r + p * v4.x;
        acc.y = acc.y * r + p * v4.y;
        acc.z = acc.z * r + p * v4.z;
        acc.w = acc.w * r + p * v4.w;
        l = l * r + p;
        m = m_new;
    }

    // ---- cross-warp merge inside the CTA ----
    __shared__ float sm[8], sl[8];
    __shared__ float sacc[8][HDIM];
    if (lane == 0) { sm[warp] = m; sl[warp] = l; }
    *reinterpret_cast<float4*>(&sacc[warp][lane * 4]) = acc;
    __syncthreads();

    if (threadIdx.x < HDIM) {
        int d = threadIdx.x;
        float gm = NEG_BIG;
        #pragma unroll
        for (int wdx = 0; wdx < 8; wdx++) gm = fmaxf(gm, sm[wdx]);
        float lt = 0.f, at = 0.f;
        #pragma unroll
        for (int wdx = 0; wdx < 8; wdx++) {
            float f = __expf(sm[wdx] - gm);
            lt += sl[wdx] * f;
            at += sacc[wdx][d] * f;
        }
        int idx = (b * HEADS + h) * NCHUNK + chunk;
        if (d == 0) { g_pm[idx] = gm; g_pl[idx] = lt; }
        g_pacc[(size_t)idx * HDIM + d] = at;
    }
}

// ---------------------------------------------------------------------------
// Kernel 2: merge <=16 chunk-partials (fully unrolled, select-masked so all
// loads issue with high MLP), normalize, add residual.
// Grid: (HEADS, BATCH), 128 threads (one per dim).
// ---------------------------------------------------------------------------
__global__ __launch_bounds__(128) void combine_kernel(const float* __restrict__ hidden,
                                                      const int*   __restrict__ ctx_lens,
                                                      float*       __restrict__ out) {
    int h = blockIdx.x, b = blockIdx.y;
    int d = threadIdx.x;
    int ctx = ctx_lens[b];
    int nc = (ctx + CHUNK - 1) / CHUNK;
    int base = (b * HEADS + h) * NCHUNK;

    // Load all NCHUNK partial stats unconditionally (valid __device__ storage),
    // then select-mask. Invalid slots may hold stale garbage/NaN: the select
    // happens BEFORE any arithmetic so nothing propagates.
    float pm[NCHUNK], pl[NCHUNK], pa[NCHUNK];
    #pragma unroll
    for (int c = 0; c < NCHUNK; c++) {
        pm[c] = g_pm[base + c];
        pl[c] = g_pl[base + c];
        pa[c] = g_pacc[(size_t)(base + c) * HDIM + d];
    }
    #pragma unroll
    for (int c = 0; c < NCHUNK; c++) {
        bool valid = (c < nc);
        pm[c] = valid ? pm[c] : NEG_BIG;
        pl[c] = valid ? pl[c] : 0.f;
        pa[c] = valid ? pa[c] : 0.f;
    }

    float gm = NEG_BIG;
    #pragma unroll
    for (int c = 0; c < NCHUNK; c++) gm = fmaxf(gm, pm[c]);
    float lt = 0.f, at = 0.f;
    #pragma unroll
    for (int c = 0; c < NCHUNK; c++) {
        float f = __expf(pm[c] - gm);   // invalid: exp(-1e30 - gm) -> 0
        lt += pl[c] * f;
        at += pa[c] * f;
    }

    int o = b * HIDDEN + h * HDIM + d;
    out[o] = hidden[o] + at / lt;
}

// ---------------------------------------------------------------------------
extern "C" void kernel_launch(void* const* d_in, const int* in_sizes, int n_in,
                              void* d_out, int out_size) {
    const float* hidden = (const float*)d_in[0];   // [B, 4096] f32
    const float* kc     = (const float*)d_in[1];   // [NB, BS, H, D] f32
    const float* vc     = (const float*)d_in[2];   // [NB, BS, H, D] f32
    const int*   bt     = (const int*)  d_in[3];   // [B, MB] i32
    const int*   ctx    = (const int*)  d_in[4];   // [B] i32
    const float* w      = (const float*)d_in[5];   // [4096] f32
    float* out = (float*)d_out;                    // [B, 4096] f32

    dim3 g(NCHUNK, HEADS, BATCH);
    attn_kernel<<<g, 256>>>(hidden, w, kc, vc, bt, ctx);
    combine_kernel<<<dim3(HEADS, BATCH), HDIM>>>(hidden, ctx, out);
}

// round 11
// speedup vs baseline: 1.1058x; 1.1058x over previous
#include <cuda_runtime.h>
#include <math.h>

#define BATCH   16
#define HEADS   32
#define HDIM    128
#define NBLK    1024
#define BLKSZ   16
#define MAXB    128
#define HIDDEN  (HEADS * HDIM)      // 4096
#define S_MAX   (MAXB * BLKSZ)      // 2048
#define CHUNK   256
#define NCHUNK  (S_MAX / CHUNK)     // 8
#define EPS     1e-6f
#define NEG_BIG (-1e30f)
#define QK_SCALE 0.08838834764831845f   // 1/sqrt(128)

// Scratch (no allocations allowed in kernel_launch)
__device__ float g_pm[BATCH * HEADS * NCHUNK];              // per-chunk running max
__device__ float g_pl[BATCH * HEADS * NCHUNK];              // per-chunk sum(exp)
__device__ float g_pacc[BATCH * HEADS * NCHUNK * HDIM];     // per-chunk unnormalized acc

// ---------------------------------------------------------------------------
// Kernel 1: fused RMSNorm + flash-decoding partial attention (one 256-pos chunk)
// Grid: (NCHUNK, HEADS, BATCH), 256 threads = 8 warps.  (== R8 kernel, 74.9us)
// ---------------------------------------------------------------------------
__global__ __launch_bounds__(256) void attn_kernel(const float* __restrict__ hidden,
                                                   const float* __restrict__ w,
                                                   const float* __restrict__ kc,
                                                   const float* __restrict__ vc,
                                                   const int*   __restrict__ bt,
                                                   const int*   __restrict__ ctx_lens) {
    int chunk = blockIdx.x, h = blockIdx.y, b = blockIdx.z;
    int ctx = ctx_lens[b];
    int s0 = chunk * CHUNK;
    if (s0 >= ctx) return;                      // uniform across CTA: safe early exit
    int s_end = min(s0 + CHUNK, ctx);

    int warp = threadIdx.x >> 5;
    int lane = threadIdx.x & 31;

    // ---- fused RMSNorm: sum of squares over hidden[b, :] ----
    __shared__ float red[8];
    {
        const float4* xr = reinterpret_cast<const float4*>(hidden + (size_t)b * HIDDEN);
        float4 v0 = xr[threadIdx.x];
        float4 v1 = xr[threadIdx.x + 256];
        float4 v2 = xr[threadIdx.x + 512];
        float4 v3 = xr[threadIdx.x + 768];
        float ss = v0.x*v0.x + v0.y*v0.y + v0.z*v0.z + v0.w*v0.w
                 + v1.x*v1.x + v1.y*v1.y + v1.z*v1.z + v1.w*v1.w
                 + v2.x*v2.x + v2.y*v2.y + v2.z*v2.z + v2.w*v2.w
                 + v3.x*v3.x + v3.y*v3.y + v3.z*v3.z + v3.w*v3.w;
        #pragma unroll
        for (int o = 16; o; o >>= 1) ss += __shfl_xor_sync(0xffffffffu, ss, o);
        if (lane == 0) red[warp] = ss;
    }
    __syncthreads();
    float tot = red[0] + red[1] + red[2] + red[3] + red[4] + red[5] + red[6] + red[7];
    float inv = rsqrtf(tot * (1.0f / HIDDEN) + EPS) * QK_SCALE;

    // lane-private q fragment (4 contiguous floats), norm + weight folded in
    float4 q4;
    {
        size_t qo = (size_t)b * HIDDEN + h * HDIM + lane * 4;
        float4 hx = *reinterpret_cast<const float4*>(hidden + qo);
        float4 wx = *reinterpret_cast<const float4*>(w + h * HDIM + lane * 4);
        q4 = make_float4(hx.x * inv * wx.x, hx.y * inv * wx.y,
                         hx.z * inv * wx.z, hx.w * inv * wx.w);
    }

    const int* btb = bt + b * MAXB;

    float  m = NEG_BIG, l = 0.f;
    float4 acc = make_float4(0.f, 0.f, 0.f, 0.f);

    int s = s0 + warp;
    // ---- x2 unrolled mainloop: 4 outstanding 512B loads per warp ----
    for (; s + 8 < s_end; s += 16) {
        int s1 = s + 8;
        int blk0 = __ldg(btb + (s  >> 4));
        int blk1 = __ldg(btb + (s1 >> 4));
        size_t base0 = ((size_t)(blk0 * BLKSZ + (s  & 15)) * HEADS + h) * HDIM + lane * 4;
        size_t base1 = ((size_t)(blk1 * BLKSZ + (s1 & 15)) * HEADS + h) * HDIM + lane * 4;
        float4 k0 = *reinterpret_cast<const float4*>(kc + base0);
        float4 v0 = *reinterpret_cast<const float4*>(vc + base0);
        float4 k1 = *reinterpret_cast<const float4*>(kc + base1);
        float4 v1 = *reinterpret_cast<const float4*>(vc + base1);

        float d0 = k0.x*q4.x + k0.y*q4.y + k0.z*q4.z + k0.w*q4.w;
        float d1 = k1.x*q4.x + k1.y*q4.y + k1.z*q4.z + k1.w*q4.w;
        #pragma unroll
        for (int o = 16; o; o >>= 1) {          // interleaved butterflies
            d0 += __shfl_xor_sync(0xffffffffu, d0, o);
            d1 += __shfl_xor_sync(0xffffffffu, d1, o);
        }

        float m_new = fmaxf(m, fmaxf(d0, d1));
        float r  = __expf(m  - m_new);          // underflows to 0 on first iter
        float p0 = __expf(d0 - m_new);
        float p1 = __expf(d1 - m_new);
        acc.x = acc.x * r + p0 * v0.x + p1 * v1.x;
        acc.y = acc.y * r + p0 * v0.y + p1 * v1.y;
        acc.z = acc.z * r + p0 * v0.z + p1 * v1.z;
        acc.w = acc.w * r + p0 * v0.w + p1 * v1.w;
        l = l * r + p0 + p1;
        m = m_new;
    }
    // tail (at most one position per warp)
    if (s < s_end) {
        int blk = __ldg(btb + (s >> 4));
        size_t base = ((size_t)(blk * BLKSZ + (s & 15)) * HEADS + h) * HDIM + lane * 4;
        float4 k4 = *reinterpret_cast<const float4*>(kc + base);
        float4 v4 = *reinterpret_cast<const float4*>(vc + base);
        float dot = k4.x*q4.x + k4.y*q4.y + k4.z*q4.z + k4.w*q4.w;
        #pragma unroll
        for (int o = 16; o; o >>= 1) dot += __shfl_xor_sync(0xffffffffu, dot, o);
        float m_new = fmaxf(m, dot);
        float r = __expf(m - m_new);
        float p = __expf(dot - m_new);
        acc.x = acc.x * r + p * v4.x;
        acc.y = acc.y * r + p * v4.y;
        acc.z = acc.z * r + p * v4.z;
        acc.w = acc.w * r + p * v4.w;
        l = l * r + p;
        m = m_new;
    }

    // ---- cross-warp merge inside the CTA ----
    __shared__ float sm[8], sl[8];
    __shared__ float sacc[8][HDIM];
    if (lane == 0) { sm[warp] = m; sl[warp] = l; }
    *reinterpret_cast<float4*>(&sacc[warp][lane * 4]) = acc;
    __syncthreads();

    if (threadIdx.x < HDIM) {
        int d = threadIdx.x;
        float gm = NEG_BIG;
        #pragma unroll
        for (int wdx = 0; wdx < 8; wdx++) gm = fmaxf(gm, sm[wdx]);
        float lt = 0.f, at = 0.f;
        #pragma unroll
        for (int wdx = 0; wdx < 8; wdx++) {
            float f = __expf(sm[wdx] - gm);
            lt += sl[wdx] * f;
            at += sacc[wdx][d] * f;
        }
        int idx = (b * HEADS + h) * NCHUNK + chunk;
        if (d == 0) { g_pm[idx] = gm; g_pl[idx] = lt; }
        g_pacc[(size_t)idx * HDIM + d] = at;
    }
}

// ---------------------------------------------------------------------------
// Kernel 2: merge <=8 chunk-partials, fully unrolled + select-masked so all
// loads issue up front (MLP ~24), normalize, add residual.
// Grid: (HEADS, BATCH), 128 threads (one per dim).
// ---------------------------------------------------------------------------
__global__ __launch_bounds__(128) void combine_kernel(const float* __restrict__ hidden,
                                                      const int*   __restrict__ ctx_lens,
                                                      float*       __restrict__ out) {
    int h = blockIdx.x, b = blockIdx.y;
    int d = threadIdx.x;
    int ctx = ctx_lens[b];
    int nc = (ctx + CHUNK - 1) / CHUNK;
    int base = (b * HEADS + h) * NCHUNK;

    // Load all NCHUNK=8 partial stats unconditionally (valid __device__ storage),
    // then select-mask BEFORE any arithmetic so stale garbage can't propagate.
    float pm[NCHUNK], pl[NCHUNK], pa[NCHUNK];
    #pragma unroll
    for (int c = 0; c < NCHUNK; c++) {
        pm[c] = g_pm[base + c];
        pl[c] = g_pl[base + c];
        pa[c] = g_pacc[(size_t)(base + c) * HDIM + d];
    }
    #pragma unroll
    for (int c = 0; c < NCHUNK; c++) {
        bool valid = (c < nc);
        pm[c] = valid ? pm[c] : NEG_BIG;
        pl[c] = valid ? pl[c] : 0.f;
        pa[c] = valid ? pa[c] : 0.f;
    }

    float gm = NEG_BIG;
    #pragma unroll
    for (int c = 0; c < NCHUNK; c++) gm = fmaxf(gm, pm[c]);
    float lt = 0.f, at = 0.f;
    #pragma unroll
    for (int c = 0; c < NCHUNK; c++) {
        float f = __expf(pm[c] - gm);   // invalid: exp(-1e30 - gm) -> 0
        lt += pl[c] * f;
        at += pa[c] * f;
    }

    int o = b * HIDDEN + h * HDIM + d;
    out[o] = hidden[o] + at / lt;
}

// ---------------------------------------------------------------------------
extern "C" void kernel_launch(void* const* d_in, const int* in_sizes, int n_in,
                              void* d_out, int out_size) {
    const float* hidden = (const float*)d_in[0];   // [B, 4096] f32
    const float* kc     = (const float*)d_in[1];   // [NB, BS, H, D] f32
    const float* vc     = (const float*)d_in[2];   // [NB, BS, H, D] f32
    const int*   bt     = (const int*)  d_in[3];   // [B, MB] i32
    const int*   ctx    = (const int*)  d_in[4];   // [B] i32
    const float* w      = (const float*)d_in[5];   // [4096] f32
    float* out = (float*)d_out;                    // [B, 4096] f32

    dim3 g(NCHUNK, HEADS, BATCH);
    attn_kernel<<<g, 256>>>(hidden, w, kc, vc, bt, ctx);
    combine_kernel<<<dim3(HEADS, BATCH), HDIM>>>(hidden, ctx, out);
}